// round 2
// baseline (speedup 1.0000x reference)
#include <cuda_runtime.h>

#define BATCH 16
#define IMG_H 512
#define IMG_W 512
#define NPIX (IMG_H * IMG_W)          // 262144 = 2^18
#define TOTAL (BATCH * NPIX)          // 4194304
#define LOG2_NPIX 18
#define LOG2_W 9

// Scratch (allocation-free): 3 mask buffers, union-find parent, component size, per-image comp count
__device__ unsigned char g_a[TOTAL];
__device__ unsigned char g_b[TOTAL];
__device__ unsigned char g_c[TOTAL];
__device__ int g_parent[TOTAL];
__device__ int g_csize[TOTAL];
__device__ int g_ncomp[BATCH];

// Per-row half-widths of the disk structuring elements (dy = -R..R)
__constant__ int HW1[3]  = {0, 1, 0};
__constant__ int HW2[5]  = {0, 1, 2, 1, 0};
__constant__ int HW5[11] = {0, 3, 4, 4, 4, 5, 4, 4, 4, 3, 0};

__device__ __forceinline__ unsigned char* bufsel(int s) {
    return s == 0 ? g_a : (s == 1 ? g_b : g_c);
}

// ---------------------------------------------------------------------------
// Elementwise
// ---------------------------------------------------------------------------
__global__ void k_binarize(const float* __restrict__ in, int dst) {
    int g = blockIdx.x * blockDim.x + threadIdx.x;
    if (g >= TOTAL) return;
    bufsel(dst)[g] = (in[g] > 0.0f) ? 1 : 0;
}

__global__ void k_invert(int src, int dst) {
    int g = blockIdx.x * blockDim.x + threadIdx.x;
    if (g >= TOTAL) return;
    bufsel(dst)[g] = bufsel(src)[g] ? 0 : 1;
}

__global__ void k_tofloat(int src, float* __restrict__ out) {
    int g = blockIdx.x * blockDim.x + threadIdx.x;
    if (g >= TOTAL) return;
    out[g] = bufsel(src)[g] ? 1.0f : 0.0f;
}

// ---------------------------------------------------------------------------
// Morphology (disk SE). Erode: OOB counts as fg (border_value=1).
// Dilate: OOB counts as bg (border_value=0).
// ---------------------------------------------------------------------------
template <int R>
__global__ void k_erode(int src, int dst) {
    int g = blockIdx.x * blockDim.x + threadIdx.x;
    if (g >= TOTAL) return;
    const unsigned char* __restrict__ in = bufsel(src);
    int p = g & (NPIX - 1);
    int base = g - p;
    int y = p >> LOG2_W;
    int x = p & (IMG_W - 1);
    const int* hw = (R == 5) ? HW5 : (R == 2 ? HW2 : HW1);
    bool all1 = true;
#pragma unroll
    for (int dy = -R; dy <= R; dy++) {
        int yy = y + dy;
        if (yy < 0 || yy >= IMG_H) continue;   // OOB row -> treated as 1
        int h = hw[dy + R];
        int x0 = x - h; if (x0 < 0) x0 = 0;
        int x1 = x + h; if (x1 > IMG_W - 1) x1 = IMG_W - 1;
        const unsigned char* row = in + base + (yy << LOG2_W);
        for (int xx = x0; xx <= x1; xx++) {
            if (!row[xx]) { all1 = false; }
        }
        if (!all1) break;
    }
    bufsel(dst)[g] = all1 ? 1 : 0;
}

template <int R>
__global__ void k_dilate(int src, int dst) {
    int g = blockIdx.x * blockDim.x + threadIdx.x;
    if (g >= TOTAL) return;
    const unsigned char* __restrict__ in = bufsel(src);
    int p = g & (NPIX - 1);
    int base = g - p;
    int y = p >> LOG2_W;
    int x = p & (IMG_W - 1);
    const int* hw = (R == 5) ? HW5 : (R == 2 ? HW2 : HW1);
    bool any1 = false;
#pragma unroll
    for (int dy = -R; dy <= R; dy++) {
        int yy = y + dy;
        if (yy < 0 || yy >= IMG_H) continue;   // OOB row -> treated as 0
        int h = hw[dy + R];
        int x0 = x - h; if (x0 < 0) x0 = 0;
        int x1 = x + h; if (x1 > IMG_W - 1) x1 = IMG_W - 1;
        const unsigned char* row = in + base + (yy << LOG2_W);
        for (int xx = x0; xx <= x1; xx++) {
            if (row[xx]) { any1 = true; }
        }
        if (any1) break;
    }
    bufsel(dst)[g] = any1 ? 1 : 0;
}

// ---------------------------------------------------------------------------
// Connected-component labeling (4-connectivity), union-find with atomicMin.
// Invariant: parent[i] <= i for fg pixels, so find() walks strictly downward.
// ---------------------------------------------------------------------------
__device__ __forceinline__ int uf_find(int i) {
    int p = g_parent[i];
    while (p != i) { i = p; p = g_parent[i]; }
    return i;
}

__device__ void uf_merge(int a, int b) {
    while (true) {
        a = uf_find(a);
        b = uf_find(b);
        if (a == b) return;
        int lo = a < b ? a : b;
        int hi = a < b ? b : a;
        int old = atomicMin(&g_parent[hi], lo);
        if (old == hi) return;  // successfully linked
        a = lo; b = old;        // hi already had another root; retry
    }
}

__global__ void k_ccl_init(int src) {
    int g = blockIdx.x * blockDim.x + threadIdx.x;
    if (g >= TOTAL) return;
    g_parent[g] = bufsel(src)[g] ? g : -1;
    g_csize[g] = 0;
    if ((g & (NPIX - 1)) == 0) g_ncomp[g >> LOG2_NPIX] = 0;
}

__global__ void k_ccl_merge(int src) {
    int g = blockIdx.x * blockDim.x + threadIdx.x;
    if (g >= TOTAL) return;
    const unsigned char* __restrict__ m = bufsel(src);
    if (!m[g]) return;
    int p = g & (NPIX - 1);
    int x = p & (IMG_W - 1);
    int y = p >> LOG2_W;
    if (x > 0 && m[g - 1])      uf_merge(g, g - 1);
    if (y > 0 && m[g - IMG_W])  uf_merge(g, g - IMG_W);
}

__global__ void k_ccl_finalize(int src) {
    int g = blockIdx.x * blockDim.x + threadIdx.x;
    if (g >= TOTAL) return;
    if (!bufsel(src)[g]) return;
    int r = uf_find(g);
    g_parent[g] = r;
    atomicAdd(&g_csize[r], 1);
    if (r == g) atomicAdd(&g_ncomp[g >> LOG2_NPIX], 1);
}

// remove_small_objects: keep fg pixels whose component >= min_size.
// guard: only remove when the image has > 1 component.
__global__ void k_filter_obj(int src, int dst, int min_size, int guard) {
    int g = blockIdx.x * blockDim.x + threadIdx.x;
    if (g >= TOTAL) return;
    unsigned char v = bufsel(src)[g];
    unsigned char out = 0;
    if (v) {
        int r = g_parent[g];
        bool keep = g_csize[r] >= min_size;
        if (guard && g_ncomp[g >> LOG2_NPIX] <= 1) keep = true;
        out = keep ? 1 : 0;
    }
    bufsel(dst)[g] = out;
}

// hole filling: src is the bg mask (CCL already run on it).
// result fg = (not bg) OR (bg component smaller than min_size)
__global__ void k_filter_holes(int src, int dst, int min_size) {
    int g = blockIdx.x * blockDim.x + threadIdx.x;
    if (g >= TOTAL) return;
    unsigned char bg = bufsel(src)[g];
    unsigned char out;
    if (!bg) {
        out = 1;
    } else {
        out = (g_csize[g_parent[g]] < min_size) ? 1 : 0;
    }
    bufsel(dst)[g] = out;
}

// ---------------------------------------------------------------------------
// Launch
// ---------------------------------------------------------------------------
extern "C" void kernel_launch(void* const* d_in, const int* in_sizes, int n_in,
                              void* d_out, int out_size) {
    const float* in = (const float*)d_in[0];
    float* out = (float*)d_out;

    const int T = 256;
    const int Bk = TOTAL / T;

    // fg0 = input > 0  -> buf A
    k_binarize<<<Bk, T>>>(in, 0);

    // remove_small_objects(fg0, 2000, guard)  -> buf B
    k_ccl_init<<<Bk, T>>>(0);
    k_ccl_merge<<<Bk, T>>>(0);
    k_ccl_finalize<<<Bk, T>>>(0);
    k_filter_obj<<<Bk, T>>>(0, 1, 2000, 1);

    // hole filling: bg = ~fg1 -> buf C; CCL on bg; fg2 -> buf A
    k_invert<<<Bk, T>>>(1, 2);
    k_ccl_init<<<Bk, T>>>(2);
    k_ccl_merge<<<Bk, T>>>(2);
    k_ccl_finalize<<<Bk, T>>>(2);
    k_filter_holes<<<Bk, T>>>(2, 0, 301);

    // erosion disk(2): A -> B
    k_erode<2><<<Bk, T>>>(0, 1);
    // opening disk(5): erode B -> C, dilate C -> A
    k_erode<5><<<Bk, T>>>(1, 2);
    k_dilate<5><<<Bk, T>>>(2, 0);

    // remove_small_objects(fg5, 2000, guard) -> buf B
    k_ccl_init<<<Bk, T>>>(0);
    k_ccl_merge<<<Bk, T>>>(0);
    k_ccl_finalize<<<Bk, T>>>(0);
    k_filter_obj<<<Bk, T>>>(0, 1, 2000, 1);

    // dilation disk(1): B -> C
    k_dilate<1><<<Bk, T>>>(1, 2);

    // out = float(C)
    k_tofloat<<<Bk, T>>>(2, out);
}

// round 7
// speedup vs baseline: 8.6433x; 8.6433x over previous
#include <cuda_runtime.h>

typedef unsigned long long u64;
typedef unsigned int u32;

#define BATCH 16
#define IMG_H 512
#define IMG_W 512
#define NPIX (IMG_H * IMG_W)          // 262144
#define TOTAL (BATCH * NPIX)          // 4194304
#define WPR 8                         // 64-bit words per row
#define ROWS (BATCH * IMG_H)          // 8192
#define NW (TOTAL / 64)               // 65536 words
#define WPI (NPIX / 64)               // 4096 words per image

// Scratch (allocation-free)
__device__ u64 g_m0[NW];
__device__ u64 g_m1[NW];
__device__ u64 g_m2[NW];
__device__ int g_parent[TOTAL];   // union-find over run-start pixel indices
__device__ int g_csize[TOTAL];    // component size at root
__device__ int g_carry[NW];       // run-start carried into bit0 of each word
__device__ int g_ncomp[BATCH];

__device__ __forceinline__ u64* mbuf(int s) {
    return s == 0 ? g_m0 : (s == 1 ? g_m1 : g_m2);
}

// half-width of disk(R) at row offset dy (compile-time foldable)
__device__ __forceinline__ constexpr int hwval(int R, int dy) {
    int best = 0;
    for (int x = 0; x <= R; x++)
        if (x * x + dy * dy <= R * R) best = x;
    return best;
}

// ---------------------------------------------------------------------------
// Pack / unpack / invert
// ---------------------------------------------------------------------------
__global__ void k_binarize(const float* __restrict__ in, int dst) {
    int g = blockIdx.x * blockDim.x + threadIdx.x;
    if (g >= TOTAL) return;
    unsigned b = __ballot_sync(0xffffffffu, in[g] > 0.0f);
    if ((threadIdx.x & 31) == 0) ((u32*)mbuf(dst))[g >> 5] = b;
}

__global__ void k_invert(int src, int dst) {
    int w = blockIdx.x * blockDim.x + threadIdx.x;
    if (w >= NW) return;
    mbuf(dst)[w] = ~mbuf(src)[w];
}

__global__ void k_tofloat(int src, float* __restrict__ out) {
    int g = blockIdx.x * blockDim.x + threadIdx.x;
    if (g >= TOTAL) return;
    u32 w = ((const u32*)mbuf(src))[g >> 5];
    out[g] = ((w >> (g & 31)) & 1u) ? 1.0f : 0.0f;
}

// ---------------------------------------------------------------------------
// Bit-parallel morphology. Erode: OOB = 1. Dilate: OOB = 0.
// ---------------------------------------------------------------------------
template <int R>
__global__ void k_erode(int src, int dst) {
    int wg = blockIdx.x * blockDim.x + threadIdx.x;
    if (wg >= NW) return;
    const u64* __restrict__ in = mbuf(src);
    int w = wg & (WPR - 1);
    int y = (wg / WPR) & (IMG_H - 1);
    u64 acc = ~0ull;
#pragma unroll
    for (int dy = -R; dy <= R; dy++) {
        int yy = y + dy;
        if (yy < 0 || yy >= IMG_H) continue;     // OOB row counts as 1
        int rw = wg + dy * WPR;
        u64 mid = in[rw];
        u64 lo = (w == 0) ? ~0ull : in[rw - 1];
        u64 hi = (w == WPR - 1) ? ~0ull : in[rw + 1];
        u64 a = mid;
        const int h = hwval(R, dy);
#pragma unroll
        for (int k = 1; k <= h; k++) {
            a &= (mid >> k) | (hi << (64 - k));
            a &= (mid << k) | (lo >> (64 - k));
        }
        acc &= a;
        if (!acc) break;
    }
    mbuf(dst)[wg] = acc;
}

template <int R>
__global__ void k_dilate(int src, int dst) {
    int wg = blockIdx.x * blockDim.x + threadIdx.x;
    if (wg >= NW) return;
    const u64* __restrict__ in = mbuf(src);
    int w = wg & (WPR - 1);
    int y = (wg / WPR) & (IMG_H - 1);
    u64 acc = 0ull;
#pragma unroll
    for (int dy = -R; dy <= R; dy++) {
        int yy = y + dy;
        if (yy < 0 || yy >= IMG_H) continue;     // OOB row counts as 0
        int rw = wg + dy * WPR;
        u64 mid = in[rw];
        u64 lo = (w == 0) ? 0ull : in[rw - 1];
        u64 hi = (w == WPR - 1) ? 0ull : in[rw + 1];
        u64 a = mid;
        const int h = hwval(R, dy);
#pragma unroll
        for (int k = 1; k <= h; k++) {
            a |= (mid >> k) | (hi << (64 - k));
            a |= (mid << k) | (lo >> (64 - k));
        }
        acc |= a;
        if (acc == ~0ull) break;
    }
    mbuf(dst)[wg] = acc;
}

// ---------------------------------------------------------------------------
// Run-based CCL (4-connectivity)
// ---------------------------------------------------------------------------
__device__ __forceinline__ int uf_find(int i) {
    int p = g_parent[i];
    while (p != i) { i = p; p = g_parent[i]; }
    return i;
}

__device__ void uf_merge(int a, int b) {
    while (true) {
        a = uf_find(a);
        b = uf_find(b);
        if (a == b) return;
        int lo = a < b ? a : b;
        int hi = a < b ? b : a;
        int old = atomicMin(&g_parent[hi], lo);
        if (old == hi) return;
        a = lo; b = old;
    }
}

// run start for set bit j of word m (wordbase = 64*global word index)
__device__ __forceinline__ int rs_of(u64 m, int j, int carry, int wordbase) {
    u64 zmask = (~m) & ((j == 0) ? 0ull : ((1ull << j) - 1ull));
    if (zmask) return wordbase + (63 - __clzll(zmask)) + 1;
    return carry;
}

// one thread per row: compute carries, init parent/csize at run starts
__global__ void k_ccl_prep(int src) {
    int r = blockIdx.x * blockDim.x + threadIdx.x;
    if (r >= ROWS) return;
    if ((r & (IMG_H - 1)) == 0) g_ncomp[r >> 9] = 0;
    const u64* __restrict__ in = mbuf(src);
    int rowbase = r * IMG_W;
    int carry = rowbase;
    u64 prevtop = 0;
#pragma unroll
    for (int w = 0; w < WPR; w++) {
        u64 m = in[r * WPR + w];
        g_carry[r * WPR + w] = carry;
        u64 starts = m & ~((m << 1) | prevtop);
        int wb = rowbase + 64 * w;
        while (starts) {
            int j = __ffsll((long long)starts) - 1;
            starts &= starts - 1;
            int idx = wb + j;
            g_parent[idx] = idx;
            g_csize[idx] = 0;
        }
        u64 nz = ~m;
        if (nz) carry = wb + (63 - __clzll(nz)) + 1;
        prevtop = m >> 63;
    }
}

// one thread per word: union per vertical-overlap segment
__global__ void k_ccl_merge(int src) {
    int wg = blockIdx.x * blockDim.x + threadIdx.x;
    if (wg >= NW) return;
    int row = wg / WPR;
    if ((row & (IMG_H - 1)) == 0) return;       // first row of each image
    const u64* __restrict__ in = mbuf(src);
    u64 cur = in[wg], up = in[wg - WPR];
    u64 both = cur & up;
    if (!both) return;
    int cc = g_carry[wg], cu = g_carry[wg - WPR];
    int wb_c = wg * 64, wb_u = wb_c - IMG_W;
    while (both) {
        int j = __ffsll((long long)both) - 1;
        u64 run = both >> j;
        u64 inv = ~run;
        int len = inv ? (__ffsll((long long)inv) - 1) : (64 - j);
        uf_merge(rs_of(cur, j, cc, wb_c), rs_of(up, j, cu, wb_u));
        if (j + len >= 64) both = 0;
        else both &= ~(((1ull << len) - 1ull) << j);
    }
}

// one thread per word: per run segment, find root (compress), add length, count roots
__global__ void k_ccl_finalize(int src) {
    int wg = blockIdx.x * blockDim.x + threadIdx.x;
    if (wg >= NW) return;
    u64 m = mbuf(src)[wg];
    if (!m) return;
    int carry = g_carry[wg];
    int wb = wg * 64;
    int img = wg / WPI;
    while (m) {
        int j = __ffsll((long long)m) - 1;
        u64 run = m >> j;
        u64 inv = ~run;
        int len = inv ? (__ffsll((long long)inv) - 1) : (64 - j);
        int rs = rs_of(m | (m - 1) | m, j, carry, wb);  // placeholder avoided below
        rs = rs_of(m, j, carry, wb);
        int root = uf_find(rs);
        g_parent[rs] = root;                     // path compression
        atomicAdd(&g_csize[root], len);
        if (root == rs && rs == wb + j)          // run's defining start, once
            atomicAdd(&g_ncomp[img], 1);
        if (j + len >= 64) m = 0;
        else m &= ~(((1ull << len) - 1ull) << j);
    }
}

// remove_small_objects (guard: keep all when <=1 component)
__global__ void k_filter_obj(int src, int dst, int min_size, int guard) {
    int wg = blockIdx.x * blockDim.x + threadIdx.x;
    if (wg >= NW) return;
    u64 m = mbuf(src)[wg];
    u64 out = 0;
    if (m) {
        int carry = g_carry[wg];
        int wb = wg * 64;
        bool keepall = guard && (g_ncomp[wg / WPI] <= 1);
        u64 rem = m;
        while (rem) {
            int j = __ffsll((long long)rem) - 1;
            u64 run = rem >> j;
            u64 inv = ~run;
            int len = inv ? (__ffsll((long long)inv) - 1) : (64 - j);
            u64 segbits = (j + len >= 64) ? (~0ull << j)
                                          : (((1ull << len) - 1ull) << j);
            int rs = rs_of(m, j, carry, wb);
            int sz = g_csize[g_parent[rs]];
            if (keepall || sz >= min_size) out |= segbits;
            rem &= ~segbits;
        }
    }
    mbuf(dst)[wg] = out;
}

// hole filling: src is bg mask (CCL done on it). fg = ~bg | (bg comp < min_size)
__global__ void k_filter_holes(int src, int dst, int min_size) {
    int wg = blockIdx.x * blockDim.x + threadIdx.x;
    if (wg >= NW) return;
    u64 m = mbuf(src)[wg];
    u64 out = ~m;
    if (m) {
        int carry = g_carry[wg];
        int wb = wg * 64;
        u64 rem = m;
        while (rem) {
            int j = __ffsll((long long)rem) - 1;
            u64 run = rem >> j;
            u64 inv = ~run;
            int len = inv ? (__ffsll((long long)inv) - 1) : (64 - j);
            u64 segbits = (j + len >= 64) ? (~0ull << j)
                                          : (((1ull << len) - 1ull) << j);
            int rs = rs_of(m, j, carry, wb);
            if (g_csize[g_parent[rs]] < min_size) out |= segbits;
            rem &= ~segbits;
        }
    }
    mbuf(dst)[wg] = out;
}

// ---------------------------------------------------------------------------
// Launch
// ---------------------------------------------------------------------------
extern "C" void kernel_launch(void* const* d_in, const int* in_sizes, int n_in,
                              void* d_out, int out_size) {
    const float* in = (const float*)d_in[0];
    float* out = (float*)d_out;

    const int T = 256;
    const int Bpix = TOTAL / T;   // per-pixel kernels
    const int Bw = NW / T;        // per-word kernels
    const int Br = ROWS / T;      // per-row kernels

    // fg0 -> A
    k_binarize<<<Bpix, T>>>(in, 0);

    // remove_small_objects(A, 2000, guard) -> B
    k_ccl_prep<<<Br, T>>>(0);
    k_ccl_merge<<<Bw, T>>>(0);
    k_ccl_finalize<<<Bw, T>>>(0);
    k_filter_obj<<<Bw, T>>>(0, 1, 2000, 1);

    // fill holes: bg = ~B -> C; CCL(C); -> A
    k_invert<<<Bw, T>>>(1, 2);
    k_ccl_prep<<<Br, T>>>(2);
    k_ccl_merge<<<Bw, T>>>(2);
    k_ccl_finalize<<<Bw, T>>>(2);
    k_filter_holes<<<Bw, T>>>(2, 0, 301);

    // erosion disk(2): A->B ; opening disk(5): B->C->A
    k_erode<2><<<Bw, T>>>(0, 1);
    k_erode<5><<<Bw, T>>>(1, 2);
    k_dilate<5><<<Bw, T>>>(2, 0);

    // remove_small_objects(A, 2000, guard) -> B
    k_ccl_prep<<<Br, T>>>(0);
    k_ccl_merge<<<Bw, T>>>(0);
    k_ccl_finalize<<<Bw, T>>>(0);
    k_filter_obj<<<Bw, T>>>(0, 1, 2000, 1);

    // dilation disk(1): B->C ; unpack
    k_dilate<1><<<Bw, T>>>(1, 2);
    k_tofloat<<<Bpix, T>>>(2, out);
}